// round 14
// baseline (speedup 1.0000x reference)
#include <cuda_runtime.h>
#include <cuda_bf16.h>

// CenterLoss collapses: the label mask keeps only distmat[b, labels[b]]; all
// other B*(C-1) entries are 0 -> clamped to CLAMP_MIN.
// loss = (sum_b clamp(||x_b - c_{lbl_b}||^2, MIN, MAX)) / B + (C-1)*CLAMP_MIN.
// Labels are INT32 (established R2..R5).
//
// R14 (final shape): R10/R12's 2-node PDL structure (init writes mask_term;
// rows kernel RED-adds, ordered by GridDependencySynchronize) + R12 slim math
// (float4 loads, 16 lanes/row, 10 shuffles/warp) + per-WARP direct RED:
// no __syncthreads, no smem, no block-leader funnel. Single-address REDG
// pipelines at ~0.854 cyc/op in L2 and overlaps the grid drain, so 1024
// posted REDs beat a block barrier on every block's critical path.

#define BATCH 4096
#define NUM_CLASSES 100000
#define FEAT_DIM 64
#define CLAMP_MIN_F 1e-12f
#define CLAMP_MAX_F 1e12f

#define BLOCK_THREADS 256
#define WARPS_PER_BLOCK 8
#define ROWS_PER_WARP 4
#define ROWS_PER_BLOCK (WARPS_PER_BLOCK * ROWS_PER_WARP)   // 32
#define NUM_BLOCKS (BATCH / ROWS_PER_BLOCK)                // 128 -> single wave

__global__ void __launch_bounds__(32)
center_loss_init(float* __restrict__ out) {
    // (C-1) masked zeros per row -> CLAMP_MIN each; /B leaves (C-1)*MIN.
    if (threadIdx.x == 0)
        out[0] = (float)(NUM_CLASSES - 1) * CLAMP_MIN_F;
}

__global__ void __launch_bounds__(BLOCK_THREADS)
center_loss_rows(const float* __restrict__ x,
                 const float* __restrict__ centers,
                 const int* __restrict__ labels,
                 float* __restrict__ out) {
    const int warp = threadIdx.x >> 5;
    const int lane = threadIdx.x & 31;
    const int row0 = blockIdx.x * ROWS_PER_BLOCK + warp * ROWS_PER_WARP;

    // One broadcast LDG.128 for this warp's 4 labels (row0 % 4 == 0).
    const int4 lraw = *reinterpret_cast<const int4*>(labels + row0);
    // Crash guard (free): bad label -> wrong value, never a fault.
    const int lb0 = (lraw.x < 0) ? 0 : (lraw.x >= NUM_CLASSES ? NUM_CLASSES - 1 : lraw.x);
    const int lb1 = (lraw.y < 0) ? 0 : (lraw.y >= NUM_CLASSES ? NUM_CLASSES - 1 : lraw.y);
    const int lb2 = (lraw.z < 0) ? 0 : (lraw.z >= NUM_CLASSES ? NUM_CLASSES - 1 : lraw.z);
    const int lb3 = (lraw.w < 0) ? 0 : (lraw.w >= NUM_CLASSES ? NUM_CLASSES - 1 : lraw.w);

    // float4 layout: 16 lanes cover one 64-float row; warp-wide load = 2 rows.
    const bool hi = (lane >= 16);
    const int col = lane & 15;
    const int rA = row0 + (hi ? 1 : 0);       // slot 0: rows row0+0 / row0+1
    const int rB = row0 + 2 + (hi ? 1 : 0);   // slot 1: rows row0+2 / row0+3
    const int lA = hi ? lb1 : lb0;
    const int lB = hi ? lb3 : lb2;

    // 4 independent 16B loads per lane; rows are 256B-aligned & coalesced.
    const float4 xa = reinterpret_cast<const float4*>(x + (size_t)rA * FEAT_DIM)[col];
    const float4 xb = reinterpret_cast<const float4*>(x + (size_t)rB * FEAT_DIM)[col];
    const float4 ca = reinterpret_cast<const float4*>(centers + (size_t)lA * FEAT_DIM)[col];
    const float4 cb = reinterpret_cast<const float4*>(centers + (size_t)lB * FEAT_DIM)[col];

    float d;
    float a0, a1;
    d = xa.x - ca.x; a0  = d * d;
    d = xa.y - ca.y; a0 += d * d;
    d = xa.z - ca.z; a0 += d * d;
    d = xa.w - ca.w; a0 += d * d;
    d = xb.x - cb.x; a1  = d * d;
    d = xb.y - cb.y; a1 += d * d;
    d = xb.z - cb.z; a1 += d * d;
    d = xb.w - cb.w; a1 += d * d;

    // Reduce within each 16-lane half (4 steps), both slots interleaved.
    #pragma unroll
    for (int o = 8; o > 0; o >>= 1) {
        a0 += __shfl_xor_sync(0xffffffffu, a0, o);
        a1 += __shfl_xor_sync(0xffffffffu, a1, o);
    }
    // On lane 0 after this: a0/a1 = rows row0+0 / row0+2; b0/b1 = rows +1 / +3.
    const float b0 = __shfl_xor_sync(0xffffffffu, a0, 16);
    const float b1 = __shfl_xor_sync(0xffffffffu, a1, 16);

    if (lane == 0) {
        // clamp per ROW (clip-then-sum), fixed order rows 0,1,2,3.
        float s = fminf(fmaxf(a0, CLAMP_MIN_F), CLAMP_MAX_F);
        s      += fminf(fmaxf(b0, CLAMP_MIN_F), CLAMP_MAX_F);
        s      += fminf(fmaxf(a1, CLAMP_MIN_F), CLAMP_MAX_F);
        s      += fminf(fmaxf(b1, CLAMP_MIN_F), CLAMP_MAX_F);
        // Ensure the init node's out[0]=mask_term is complete & visible.
        cudaGridDependencySynchronize();
        // No-return atomic -> REDG; 1024 single-address REDs pipeline in L2
        // (~0.854 cyc/op) and overlap the grid drain. No barrier, no smem.
        atomicAdd(out, s * (1.0f / (float)BATCH));
    }
}

extern "C" void kernel_launch(void* const* d_in, const int* in_sizes, int n_in,
                              void* d_out, int out_size) {
    const float* x       = (const float*)d_in[0];
    const float* centers = (const float*)d_in[1];
    const int*   labels  = (const int*)d_in[2];
    float* out = (float*)d_out;

    center_loss_init<<<1, 32>>>(out);

    // PDL: rows launches while init is in flight; the grid-dependency sync
    // inside rows (before the REDs) provides the ordering.
    cudaLaunchConfig_t cfg = {};
    cfg.gridDim  = dim3(NUM_BLOCKS, 1, 1);
    cfg.blockDim = dim3(BLOCK_THREADS, 1, 1);
    cfg.dynamicSmemBytes = 0;
    cfg.stream = 0;   // same (capture) stream as the launch above
    cudaLaunchAttribute attr[1];
    attr[0].id = cudaLaunchAttributeProgrammaticStreamSerialization;
    attr[0].val.programmaticStreamSerializationAllowed = 1;
    cfg.attrs = attr;
    cfg.numAttrs = 1;
    cudaLaunchKernelEx(&cfg, center_loss_rows, x, centers, labels, out);
}

// round 15
// speedup vs baseline: 1.1284x; 1.1284x over previous
#include <cuda_runtime.h>
#include <cuda_bf16.h>

// CenterLoss collapses: the label mask keeps only distmat[b, labels[b]]; all
// other B*(C-1) entries are 0 -> clamped to CLAMP_MIN.
// loss = (sum_b clamp(||x_b - c_{lbl_b}||^2, MIN, MAX)) / B + (C-1)*CLAMP_MIN.
// Labels are INT32 (established R2..R5).
//
// R15 = R10 verbatim -- the measured-best configuration (6.30us, rel_err 0.0).
// Survey of the design space (R5..R14): two-kernel plain 7.14; fused fence
// 8.74; fused acq_rel 7.97; PDL+reduce 6.85; PDL+RED (this) 6.30; 1-node
// counter variants 6.50-6.53; slim-math PDL 6.53; per-warp RED 7.87. Wall
// time sits at a ~6.3us replay/launch floor; kernel-interior deltas don't
// survive into wall. Locking in the best measured point.

#define BATCH 4096
#define NUM_CLASSES 100000
#define FEAT_DIM 64
#define CLAMP_MIN_F 1e-12f
#define CLAMP_MAX_F 1e12f

#define BLOCK_THREADS 256
#define WARPS_PER_BLOCK 8
#define ROWS_PER_WARP 4
#define ROWS_PER_BLOCK (WARPS_PER_BLOCK * ROWS_PER_WARP)   // 32
#define NUM_BLOCKS (BATCH / ROWS_PER_BLOCK)                // 128 -> single wave

__global__ void __launch_bounds__(32)
center_loss_init(float* __restrict__ out) {
    // (C-1) masked zeros per row -> CLAMP_MIN each; /B leaves (C-1)*MIN.
    if (threadIdx.x == 0)
        out[0] = (float)(NUM_CLASSES - 1) * CLAMP_MIN_F;
}

__global__ void __launch_bounds__(BLOCK_THREADS)
center_loss_rows(const float* __restrict__ x,
                 const float* __restrict__ centers,
                 const int* __restrict__ labels,
                 float* __restrict__ out) {
    const int warp = threadIdx.x >> 5;
    const int lane = threadIdx.x & 31;
    const int row0 = blockIdx.x * ROWS_PER_BLOCK + warp * ROWS_PER_WARP;

    int lb[ROWS_PER_WARP];
    #pragma unroll
    for (int r = 0; r < ROWS_PER_WARP; r++) {
        int l = labels[row0 + r];
        // Crash guard (free): bad label -> wrong value, never a fault.
        lb[r] = (l < 0) ? 0 : (l >= NUM_CLASSES ? NUM_CLASSES - 1 : l);
    }

    // 8 independent 8B loads per lane; fully coalesced 256B rows.
    float2 xv[ROWS_PER_WARP], cv[ROWS_PER_WARP];
    #pragma unroll
    for (int r = 0; r < ROWS_PER_WARP; r++)
        xv[r] = reinterpret_cast<const float2*>(x + (size_t)(row0 + r) * FEAT_DIM)[lane];
    #pragma unroll
    for (int r = 0; r < ROWS_PER_WARP; r++)
        cv[r] = reinterpret_cast<const float2*>(centers + (size_t)lb[r] * FEAT_DIM)[lane];

    float a[ROWS_PER_WARP];
    #pragma unroll
    for (int r = 0; r < ROWS_PER_WARP; r++) {
        const float d0 = xv[r].x - cv[r].x;
        const float d1 = xv[r].y - cv[r].y;
        a[r] = d0 * d0 + d1 * d1;
    }

    #pragma unroll
    for (int o = 16; o > 0; o >>= 1) {
        #pragma unroll
        for (int r = 0; r < ROWS_PER_WARP; r++)
            a[r] += __shfl_xor_sync(0xffffffffu, a[r], o);
    }

    __shared__ float ws[WARPS_PER_BLOCK];
    if (lane == 0) {
        // clamp per ROW (clip-then-sum, faithful to reference), fixed order
        float s = 0.0f;
        #pragma unroll
        for (int r = 0; r < ROWS_PER_WARP; r++)
            s += fminf(fmaxf(a[r], CLAMP_MIN_F), CLAMP_MAX_F);
        ws[warp] = s;
    }
    __syncthreads();

    if (threadIdx.x == 0) {
        float v = 0.0f;
        #pragma unroll
        for (int w = 0; w < WARPS_PER_BLOCK; w++) v += ws[w];
        // Ensure the init kernel's out[0]=mask_term is complete & visible.
        cudaGridDependencySynchronize();
        // No-return atomic add -> RED. 128 single-address REDs ~ 110 cycles.
        atomicAdd(out, v * (1.0f / (float)BATCH));
    }
}

extern "C" void kernel_launch(void* const* d_in, const int* in_sizes, int n_in,
                              void* d_out, int out_size) {
    const float* x       = (const float*)d_in[0];
    const float* centers = (const float*)d_in[1];
    const int*   labels  = (const int*)d_in[2];
    float* out = (float*)d_out;

    center_loss_init<<<1, 32>>>(out);

    // PDL: rows launches while init is in flight; the grid-dependency sync
    // inside rows (before the REDs) provides the ordering.
    cudaLaunchConfig_t cfg = {};
    cfg.gridDim  = dim3(NUM_BLOCKS, 1, 1);
    cfg.blockDim = dim3(BLOCK_THREADS, 1, 1);
    cfg.dynamicSmemBytes = 0;
    cfg.stream = 0;   // same (capture) stream as the launch above
    cudaLaunchAttribute attr[1];
    attr[0].id = cudaLaunchAttributeProgrammaticStreamSerialization;
    attr[0].val.programmaticStreamSerializationAllowed = 1;
    cfg.attrs = attr;
    cfg.numAttrs = 1;
    cudaLaunchKernelEx(&cfg, center_loss_rows, x, centers, labels, out);
}

// round 16
// speedup vs baseline: 1.1549x; 1.0235x over previous
#include <cuda_runtime.h>
#include <cuda_bf16.h>

// CenterLoss collapses: the label mask keeps only distmat[b, labels[b]]; all
// other B*(C-1) entries are 0 -> clamped to CLAMP_MIN.
// loss = (sum_b clamp(||x_b - c_{lbl_b}||^2, MIN, MAX)) / B + (C-1)*CLAMP_MIN.
// Labels are INT32 (established R2..R5).
//
// R16 = R10 structure (2-node PDL + block-leader RED, the best family) with
// HALF the CTAs: 64 blocks x 512 threads. R15 (source-identical to R10)
// measured 6.98 vs R10's 6.30 -> run noise ~±0.35us; the only lever with
// plausibly observable magnitude is the CTA launch/drain envelope: half the
// launch ramp, half the GridDependencySync executions, half the REDs, half
// the completion drain. Per-warp math is byte-identical to R10.

#define BATCH 4096
#define NUM_CLASSES 100000
#define FEAT_DIM 64
#define CLAMP_MIN_F 1e-12f
#define CLAMP_MAX_F 1e12f

#define BLOCK_THREADS 512
#define WARPS_PER_BLOCK 16
#define ROWS_PER_WARP 4
#define ROWS_PER_BLOCK (WARPS_PER_BLOCK * ROWS_PER_WARP)   // 64
#define NUM_BLOCKS (BATCH / ROWS_PER_BLOCK)                // 64 -> single wave

__global__ void __launch_bounds__(32)
center_loss_init(float* __restrict__ out) {
    // (C-1) masked zeros per row -> CLAMP_MIN each; /B leaves (C-1)*MIN.
    if (threadIdx.x == 0)
        out[0] = (float)(NUM_CLASSES - 1) * CLAMP_MIN_F;
}

__global__ void __launch_bounds__(BLOCK_THREADS)
center_loss_rows(const float* __restrict__ x,
                 const float* __restrict__ centers,
                 const int* __restrict__ labels,
                 float* __restrict__ out) {
    const int warp = threadIdx.x >> 5;
    const int lane = threadIdx.x & 31;
    const int row0 = blockIdx.x * ROWS_PER_BLOCK + warp * ROWS_PER_WARP;

    int lb[ROWS_PER_WARP];
    #pragma unroll
    for (int r = 0; r < ROWS_PER_WARP; r++) {
        int l = labels[row0 + r];
        // Crash guard (free): bad label -> wrong value, never a fault.
        lb[r] = (l < 0) ? 0 : (l >= NUM_CLASSES ? NUM_CLASSES - 1 : l);
    }

    // 8 independent 8B loads per lane; fully coalesced 256B rows.
    float2 xv[ROWS_PER_WARP], cv[ROWS_PER_WARP];
    #pragma unroll
    for (int r = 0; r < ROWS_PER_WARP; r++)
        xv[r] = reinterpret_cast<const float2*>(x + (size_t)(row0 + r) * FEAT_DIM)[lane];
    #pragma unroll
    for (int r = 0; r < ROWS_PER_WARP; r++)
        cv[r] = reinterpret_cast<const float2*>(centers + (size_t)lb[r] * FEAT_DIM)[lane];

    float a[ROWS_PER_WARP];
    #pragma unroll
    for (int r = 0; r < ROWS_PER_WARP; r++) {
        const float d0 = xv[r].x - cv[r].x;
        const float d1 = xv[r].y - cv[r].y;
        a[r] = d0 * d0 + d1 * d1;
    }

    #pragma unroll
    for (int o = 16; o > 0; o >>= 1) {
        #pragma unroll
        for (int r = 0; r < ROWS_PER_WARP; r++)
            a[r] += __shfl_xor_sync(0xffffffffu, a[r], o);
    }

    __shared__ float ws[WARPS_PER_BLOCK];
    if (lane == 0) {
        // clamp per ROW (clip-then-sum, faithful to reference), fixed order
        float s = 0.0f;
        #pragma unroll
        for (int r = 0; r < ROWS_PER_WARP; r++)
            s += fminf(fmaxf(a[r], CLAMP_MIN_F), CLAMP_MAX_F);
        ws[warp] = s;
    }
    __syncthreads();

    if (threadIdx.x == 0) {
        float v = 0.0f;
        #pragma unroll
        for (int w = 0; w < WARPS_PER_BLOCK; w++) v += ws[w];
        // Ensure the init kernel's out[0]=mask_term is complete & visible.
        cudaGridDependencySynchronize();
        // No-return atomic add -> RED. 64 single-address REDs ~ 55 cycles.
        atomicAdd(out, v * (1.0f / (float)BATCH));
    }
}

extern "C" void kernel_launch(void* const* d_in, const int* in_sizes, int n_in,
                              void* d_out, int out_size) {
    const float* x       = (const float*)d_in[0];
    const float* centers = (const float*)d_in[1];
    const int*   labels  = (const int*)d_in[2];
    float* out = (float*)d_out;

    center_loss_init<<<1, 32>>>(out);

    // PDL: rows launches while init is in flight; the grid-dependency sync
    // inside rows (before the REDs) provides the ordering.
    cudaLaunchConfig_t cfg = {};
    cfg.gridDim  = dim3(NUM_BLOCKS, 1, 1);
    cfg.blockDim = dim3(BLOCK_THREADS, 1, 1);
    cfg.dynamicSmemBytes = 0;
    cfg.stream = 0;   // same (capture) stream as the launch above
    cudaLaunchAttribute attr[1];
    attr[0].id = cudaLaunchAttributeProgrammaticStreamSerialization;
    attr[0].val.programmaticStreamSerializationAllowed = 1;
    cfg.attrs = attr;
    cfg.numAttrs = 1;
    cudaLaunchKernelEx(&cfg, center_loss_rows, x, centers, labels, out);
}

// round 17
// speedup vs baseline: 1.2746x; 1.1036x over previous
#include <cuda_runtime.h>
#include <cuda_bf16.h>

// CenterLoss collapses: the label mask keeps only distmat[b, labels[b]]; all
// other B*(C-1) entries are 0 -> clamped to CLAMP_MIN.
// loss = (sum_b clamp(||x_b - c_{lbl_b}||^2, MIN, MAX)) / B + (C-1)*CLAMP_MIN.
// Labels are INT32 (established R2..R5).
//
// R17 (final) = the two independently-best features combined:
//   - 64 CTAs x 512 threads (R16: best kernel dur 5.73us; halved
//     launch/drain/GridDepSync envelope)
//   - float4 slim math (R12: 4 LDGs + 10 shuffles per warp vs 8 + 20)
// Structure: 2-node PDL (init writes mask_term; rows kernel block-leader
// RED-adds, ordered by one GridDependencySynchronize per block) -- the
// sync-minimal shape that won the R5..R16 structural survey.

#define BATCH 4096
#define NUM_CLASSES 100000
#define FEAT_DIM 64
#define CLAMP_MIN_F 1e-12f
#define CLAMP_MAX_F 1e12f

#define BLOCK_THREADS 512
#define WARPS_PER_BLOCK 16
#define ROWS_PER_WARP 4
#define ROWS_PER_BLOCK (WARPS_PER_BLOCK * ROWS_PER_WARP)   // 64
#define NUM_BLOCKS (BATCH / ROWS_PER_BLOCK)                // 64 -> single wave

__global__ void __launch_bounds__(32)
center_loss_init(float* __restrict__ out) {
    // (C-1) masked zeros per row -> CLAMP_MIN each; /B leaves (C-1)*MIN.
    if (threadIdx.x == 0)
        out[0] = (float)(NUM_CLASSES - 1) * CLAMP_MIN_F;
}

__global__ void __launch_bounds__(BLOCK_THREADS)
center_loss_rows(const float* __restrict__ x,
                 const float* __restrict__ centers,
                 const int* __restrict__ labels,
                 float* __restrict__ out) {
    const int warp = threadIdx.x >> 5;
    const int lane = threadIdx.x & 31;
    const int row0 = blockIdx.x * ROWS_PER_BLOCK + warp * ROWS_PER_WARP;

    // One broadcast LDG.128 for this warp's 4 labels (row0 % 4 == 0).
    const int4 lraw = *reinterpret_cast<const int4*>(labels + row0);
    // Crash guard (free): bad label -> wrong value, never a fault.
    const int lb0 = (lraw.x < 0) ? 0 : (lraw.x >= NUM_CLASSES ? NUM_CLASSES - 1 : lraw.x);
    const int lb1 = (lraw.y < 0) ? 0 : (lraw.y >= NUM_CLASSES ? NUM_CLASSES - 1 : lraw.y);
    const int lb2 = (lraw.z < 0) ? 0 : (lraw.z >= NUM_CLASSES ? NUM_CLASSES - 1 : lraw.z);
    const int lb3 = (lraw.w < 0) ? 0 : (lraw.w >= NUM_CLASSES ? NUM_CLASSES - 1 : lraw.w);

    // float4 layout: 16 lanes cover one 64-float row; warp-wide load = 2 rows.
    const bool hi = (lane >= 16);
    const int col = lane & 15;
    const int rA = row0 + (hi ? 1 : 0);       // slot 0: rows row0+0 / row0+1
    const int rB = row0 + 2 + (hi ? 1 : 0);   // slot 1: rows row0+2 / row0+3
    const int lA = hi ? lb1 : lb0;
    const int lB = hi ? lb3 : lb2;

    // 4 independent 16B loads per lane; rows are 256B-aligned & coalesced.
    const float4 xa = reinterpret_cast<const float4*>(x + (size_t)rA * FEAT_DIM)[col];
    const float4 xb = reinterpret_cast<const float4*>(x + (size_t)rB * FEAT_DIM)[col];
    const float4 ca = reinterpret_cast<const float4*>(centers + (size_t)lA * FEAT_DIM)[col];
    const float4 cb = reinterpret_cast<const float4*>(centers + (size_t)lB * FEAT_DIM)[col];

    float d;
    float a0, a1;
    d = xa.x - ca.x; a0  = d * d;
    d = xa.y - ca.y; a0 += d * d;
    d = xa.z - ca.z; a0 += d * d;
    d = xa.w - ca.w; a0 += d * d;
    d = xb.x - cb.x; a1  = d * d;
    d = xb.y - cb.y; a1 += d * d;
    d = xb.z - cb.z; a1 += d * d;
    d = xb.w - cb.w; a1 += d * d;

    // Reduce within each 16-lane half (4 steps), both slots interleaved.
    #pragma unroll
    for (int o = 8; o > 0; o >>= 1) {
        a0 += __shfl_xor_sync(0xffffffffu, a0, o);
        a1 += __shfl_xor_sync(0xffffffffu, a1, o);
    }
    // On lane 0 after this: a0/a1 = rows row0+0 / row0+2; b0/b1 = rows +1 / +3.
    const float b0 = __shfl_xor_sync(0xffffffffu, a0, 16);
    const float b1 = __shfl_xor_sync(0xffffffffu, a1, 16);

    __shared__ float ws[WARPS_PER_BLOCK];
    if (lane == 0) {
        // clamp per ROW (clip-then-sum), fixed order rows 0,1,2,3.
        float s = fminf(fmaxf(a0, CLAMP_MIN_F), CLAMP_MAX_F);
        s      += fminf(fmaxf(b0, CLAMP_MIN_F), CLAMP_MAX_F);
        s      += fminf(fmaxf(a1, CLAMP_MIN_F), CLAMP_MAX_F);
        s      += fminf(fmaxf(b1, CLAMP_MIN_F), CLAMP_MAX_F);
        ws[warp] = s;
    }
    __syncthreads();

    if (threadIdx.x == 0) {
        float v = 0.0f;
        #pragma unroll
        for (int w = 0; w < WARPS_PER_BLOCK; w++) v += ws[w];
        // Ensure the init node's out[0]=mask_term is complete & visible.
        cudaGridDependencySynchronize();
        // No-return atomic add -> RED. 64 single-address REDs ~ 55 cycles.
        atomicAdd(out, v * (1.0f / (float)BATCH));
    }
}

extern "C" void kernel_launch(void* const* d_in, const int* in_sizes, int n_in,
                              void* d_out, int out_size) {
    const float* x       = (const float*)d_in[0];
    const float* centers = (const float*)d_in[1];
    const int*   labels  = (const int*)d_in[2];
    float* out = (float*)d_out;

    center_loss_init<<<1, 32>>>(out);

    // PDL: rows launches while init is in flight; the grid-dependency sync
    // inside rows (before the REDs) provides the ordering.
    cudaLaunchConfig_t cfg = {};
    cfg.gridDim  = dim3(NUM_BLOCKS, 1, 1);
    cfg.blockDim = dim3(BLOCK_THREADS, 1, 1);
    cfg.dynamicSmemBytes = 0;
    cfg.stream = 0;   // same (capture) stream as the launch above
    cudaLaunchAttribute attr[1];
    attr[0].id = cudaLaunchAttributeProgrammaticStreamSerialization;
    attr[0].val.programmaticStreamSerializationAllowed = 1;
    cfg.attrs = attr;
    cfg.numAttrs = 1;
    cudaLaunchKernelEx(&cfg, center_loss_rows, x, centers, labels, out);
}